// round 8
// baseline (speedup 1.0000x reference)
#include <cuda_runtime.h>
#include <cstdint>

// ---------------- problem constants ----------------
#define NS_PER   12500
#define AEVD     1008
#define KPAD1    1024
#define D1       256
#define D2       192
#define D3       160
#define ENS      8
#define NSPECIES 4
#define TM       128
#define NTILES   98
#define NATOM    50000
#define NSE      32
#define NBLOCKS  (ENS * NTILES * NSPECIES)

#define NC1 32    // KPAD1/32
#define NC2 8     // D1/32
#define NC3 6     // D2/32

// ---------------- persistent bf16 plane scratch ----------------
__device__ uint16_t g_aevH[(size_t)NATOM * KPAD1];
__device__ uint16_t g_aevL[(size_t)NATOM * KPAD1];
__device__ uint16_t g_w1H[(size_t)NSE * D1 * KPAD1];
__device__ uint16_t g_w1L[(size_t)NSE * D1 * KPAD1];
__device__ uint16_t g_w2H[(size_t)NSE * D2 * D1];
__device__ uint16_t g_w2L[(size_t)NSE * D2 * D1];
__device__ uint16_t g_w3H[(size_t)NSE * D3 * D2];
__device__ uint16_t g_w3L[(size_t)NSE * D3 * D2];
__device__ double g_scratch;
__device__ int    g_done;

// ---------------- smem layout (bytes) ----------------
#define RI_OFF   0                          // 128 ints
#define RED_OFF  512                        // 256 floats
#define PL       4096
// L1 3-stage staging: per stage Ah(10240) Al(10240) Bh(20480) Bl(20480) = 61440
#define STG      61440
#define APL(st,p) (PL + (st)*STG + (p)*10240)
#define BPL(st,p) (PL + (st)*STG + 20480 + (p)*20480)
// h planes (overwrite staging after L1)
#define HH       PL                         // [128][264] bf16
#define HL       (PL + 67584)
// W2/W3 2-stage staging after H region
#define WPL(b,p) (PL + 135168 + (b)*30720 + (p)*15360)
#define SMEM_BYTES (PL + 135168 + 61440)    // 200704

// ---------------- helpers ----------------
__device__ __forceinline__ uint32_t cvt2(float v0, float v1) {  // v0->lo16, v1->hi16
    uint32_t r;
    asm("cvt.rn.bf16x2.f32 %0, %1, %2;" : "=r"(r) : "f"(v1), "f"(v0));
    return r;
}
__device__ __forceinline__ float lo16f(uint32_t h) { return __uint_as_float(h << 16); }
__device__ __forceinline__ float hi16f(uint32_t h) { return __uint_as_float(h & 0xFFFF0000u); }

__device__ __forceinline__ float celu01(float x) {
    return x > 0.f ? x : 0.1f * (__expf(x * 10.f) - 1.f);
}

__device__ __forceinline__ void mma16(float d[4], const uint32_t a[4], const uint32_t b[2]) {
    asm volatile(
        "mma.sync.aligned.m16n8k16.row.col.f32.bf16.bf16.f32 "
        "{%0,%1,%2,%3},{%4,%5,%6,%7},{%8,%9},{%0,%1,%2,%3};\n"
        : "+f"(d[0]), "+f"(d[1]), "+f"(d[2]), "+f"(d[3])
        : "r"(a[0]), "r"(a[1]), "r"(a[2]), "r"(a[3]), "r"(b[0]), "r"(b[1]));
}

__device__ __forceinline__ void ldm4(uint32_t* r, uint32_t addr) {
    asm volatile("ldmatrix.sync.aligned.m8n8.x4.shared.b16 {%0,%1,%2,%3}, [%4];"
                 : "=r"(r[0]), "=r"(r[1]), "=r"(r[2]), "=r"(r[3]) : "r"(addr));
}
__device__ __forceinline__ void ldm2(uint32_t* r, uint32_t addr) {
    asm volatile("ldmatrix.sync.aligned.m8n8.x2.shared.b16 {%0,%1}, [%2];"
                 : "=r"(r[0]), "=r"(r[1]) : "r"(addr));
}

__device__ __forceinline__ void cp16(uint32_t dst, const void* src, int szbytes) {
    asm volatile("cp.async.ca.shared.global [%0], [%1], 16, %2;\n"
                 :: "r"(dst), "l"(src), "r"(szbytes));
}
#define CP_COMMIT()  asm volatile("cp.async.commit_group;\n" ::)
#define CP_WAIT1()   asm volatile("cp.async.wait_group 1;\n" ::)
#define CP_WAIT0()   asm volatile("cp.async.wait_group 0;\n" ::)

// ---------------- merged pre-pass (also resets accumulators) ----------------
#define T_AEV ((long)NATOM * (KPAD1 / 2))
#define T_W1  ((long)NSE * D1 * (KPAD1 / 2))
#define T_W2  ((long)NSE * D2 * (D1 / 2))
#define T_W3  ((long)NSE * D3 * (D2 / 2))
#define T_ALL (T_AEV + T_W1 + T_W2 + T_W3)

__global__ void prep_all(const float* __restrict__ aev, const float* __restrict__ W1,
                         const float* __restrict__ W2, const float* __restrict__ W3)
{
    long t = (long)blockIdx.x * 256 + threadIdx.x;
    if (t == 0) { g_scratch = 0.0; g_done = 0; }
    if (t >= T_ALL) return;

    if (t < T_AEV) {
        long a  = t / (KPAD1 / 2);
        int  kp = (int)(t - a * (KPAD1 / 2));
        int  k  = 2 * kp;
        float v0 = (k     < AEVD) ? aev[(size_t)a * AEVD + k]     : 0.f;
        float v1 = (k + 1 < AEVD) ? aev[(size_t)a * AEVD + k + 1] : 0.f;
        uint32_t h = cvt2(v0, v1);
        uint32_t l = cvt2(v0 - lo16f(h), v1 - hi16f(h));
        ((uint32_t*)g_aevH)[t] = h;
        ((uint32_t*)g_aevL)[t] = l;
        return;
    }
    const float* W; uint16_t *dH, *dL; int K, N, Kpad; long u;
    if (t < T_AEV + T_W1)      { u = t - T_AEV;        W = W1; dH = g_w1H; dL = g_w1L; K = AEVD; N = D1; Kpad = KPAD1; }
    else if (t < T_AEV + T_W1 + T_W2) { u = t - T_AEV - T_W1; W = W2; dH = g_w2H; dL = g_w2L; K = D1; N = D2; Kpad = D1; }
    else                       { u = t - T_AEV - T_W1 - T_W2; W = W3; dH = g_w3H; dL = g_w3L; K = D2; N = D3; Kpad = D2; }
    int n  = (int)(u % N);
    long r = u / N;
    int kp = (int)(r % (Kpad / 2));
    int se = (int)(r / (Kpad / 2));
    int k  = 2 * kp;
    float v0 = (k     < K) ? W[((size_t)se * K + k) * N + n]     : 0.f;
    float v1 = (k + 1 < K) ? W[((size_t)se * K + k + 1) * N + n] : 0.f;
    uint32_t h = cvt2(v0, v1);
    uint32_t l = cvt2(v0 - lo16f(h), v1 - hi16f(h));
    size_t di = ((size_t)se * N + n) * (Kpad / 2) + kp;
    ((uint32_t*)dH)[di] = h;
    ((uint32_t*)dL)[di] = l;
}

// ---------------- main fused kernel (256 threads, 2x4 warp grid) ----------------
__global__ void __launch_bounds__(256, 1)
ani_main(const float* __restrict__ B1, const float* __restrict__ B2,
         const float* __restrict__ B3, const float* __restrict__ W4,
         const float* __restrict__ B4, const int* __restrict__ idx,
         float* __restrict__ out)
{
    extern __shared__ char smc[];
    const uint32_t smem_base = (uint32_t)__cvta_generic_to_shared(smc);
    int*   rowIdx = (int*)(smc + RI_OFF);
    float* red    = (float*)(smc + RED_OFF);

    const int e    = blockIdx.x;
    const int tile = blockIdx.y;
    const int s    = blockIdx.z;
    const int se   = s * ENS + e;

    const int tid  = threadIdx.x;
    const int lane = tid & 31;
    const int warp = tid >> 5;
    const int gid  = lane >> 2;
    const int tig  = lane & 3;
    const int wm   = warp & 1;      // 2 M-row halves of 64
    const int wn   = warp >> 1;     // 4 N cols
    const int mB   = wm * 64;

    const int amrow = (lane & 7) + (lane & 8);
    const int akoff = (lane & 16) >> 1;
    const int bnrow = (lane & 7) + ((lane & 16) >> 1);
    const int bkoff = lane & 8;

    const int tileBase = tile * TM;
    const int valid    = min(TM, NS_PER - tileBase);

    if (tid < TM)
        rowIdx[tid] = (tid < valid) ? idx[s * NS_PER + tileBase + tid] : -1;
    __syncthreads();

    const float* b1g = B1 + (size_t)se * D1;
    const float* b2g = B2 + (size_t)se * D2;
    const float* b3g = B3 + (size_t)se * D3;
    const float* w4g = W4 + (size_t)se * D3;

    // ---------------- cp.async issue helpers (256 threads) ----------------
    auto issueA1 = [&](int kc, int st) {
        #pragma unroll
        for (int it = 0; it < 4; ++it) {
            int t = tid + it * 256;          // 0..1023
            int p   = t >> 9;
            int rem = t & 511;
            int r   = rem >> 2;
            int seg = rem & 3;
            int g   = rowIdx[r];
            const uint16_t* base = p ? g_aevL : g_aevH;
            const uint16_t* src  = base + ((size_t)(g < 0 ? 0 : g) * KPAD1 + kc * 32 + seg * 8);
            cp16(smem_base + APL(st, p) + (r * 40 + seg * 8) * 2, src, g >= 0 ? 16 : 0);
        }
    };
    auto issueB1 = [&](int kc, int st) {
        #pragma unroll
        for (int it = 0; it < 8; ++it) {
            int t = tid + it * 256;          // 0..2047
            int p   = t >> 10;
            int rem = t & 1023;
            int n   = rem >> 2;
            int seg = rem & 3;
            const uint16_t* base = p ? g_w1L : g_w1H;
            cp16(smem_base + BPL(st, p) + (n * 40 + seg * 8) * 2,
                 base + ((size_t)(se * D1 + n) * KPAD1 + kc * 32 + seg * 8), 16);
        }
        CP_COMMIT();
    };
    auto issueW2 = [&](int kc, int b) {
        #pragma unroll
        for (int it = 0; it < 6; ++it) {
            int t = tid + it * 256;          // 0..1535
            int p   = t >= 768;
            int rem = t - p * 768;
            int n   = rem >> 2;
            int seg = rem & 3;
            const uint16_t* base = p ? g_w2L : g_w2H;
            cp16(smem_base + WPL(b, p) + (n * 40 + seg * 8) * 2,
                 base + ((size_t)(se * D2 + n) * D1 + kc * 32 + seg * 8), 16);
        }
        CP_COMMIT();
    };
    auto issueW3 = [&](int kc, int b) {
        #pragma unroll
        for (int it = 0; it < 5; ++it) {
            int t = tid + it * 256;          // 0..1279
            int p   = t >= 640;
            int rem = t - p * 640;
            int n   = rem >> 2;
            int seg = rem & 3;
            const uint16_t* base = p ? g_w3L : g_w3H;
            cp16(smem_base + WPL(b, p) + (n * 40 + seg * 8) * 2,
                 base + ((size_t)(se * D3 + n) * D2 + kc * 32 + seg * 8), 16);
        }
        CP_COMMIT();
    };

    // ==================== Layer 1: 3-stage, 1 sync/chunk ====================
    {
        const int nB = wn * 64;
        float acc[4][8][4];
        #pragma unroll
        for (int mi = 0; mi < 4; mi++)
            #pragma unroll
            for (int j = 0; j < 8; j++)
                #pragma unroll
                for (int q = 0; q < 4; q++) acc[mi][j][q] = 0.f;

        issueA1(0, 0); issueB1(0, 0);
        issueA1(1, 1); issueB1(1, 1);
        for (int kc = 0; kc < NC1; ++kc) {
            const int st = kc % 3;
            if (kc == NC1 - 1) CP_WAIT0(); else CP_WAIT1();
            __syncthreads();
            if (kc + 2 < NC1) {
                int ns = (kc + 2) % 3;
                issueA1(kc + 2, ns); issueB1(kc + 2, ns);
            }
            #pragma unroll
            for (int ks = 0; ks < 2; ++ks) {
                const int k0 = ks * 16;
                uint32_t AH[4][4], AL[4][4];
                #pragma unroll
                for (int mi = 0; mi < 4; mi++) {
                    uint32_t aaddr = smem_base + APL(st, 0)
                                   + ((mB + mi * 16 + amrow) * 40 + k0 + akoff) * 2;
                    ldm4(AH[mi], aaddr);
                    ldm4(AL[mi], aaddr + 10240);
                }
                #pragma unroll
                for (int jp = 0; jp < 4; ++jp) {
                    uint32_t baddr = smem_base + BPL(st, 0)
                                   + ((nB + jp * 16 + bnrow) * 40 + k0 + bkoff) * 2;
                    uint32_t BH[4], BL[4];
                    ldm4(BH, baddr);
                    ldm4(BL, baddr + 20480);
                    // term-major: acc reuse distance 8
                    #pragma unroll
                    for (int mi = 0; mi < 4; mi++) {
                        mma16(acc[mi][2 * jp],     AH[mi], BH);
                        mma16(acc[mi][2 * jp + 1], AH[mi], BH + 2);
                    }
                    #pragma unroll
                    for (int mi = 0; mi < 4; mi++) {
                        mma16(acc[mi][2 * jp],     AL[mi], BH);
                        mma16(acc[mi][2 * jp + 1], AL[mi], BH + 2);
                    }
                    #pragma unroll
                    for (int mi = 0; mi < 4; mi++) {
                        mma16(acc[mi][2 * jp],     AH[mi], BL);
                        mma16(acc[mi][2 * jp + 1], AH[mi], BL + 2);
                    }
                }
            }
        }
        __syncthreads();      // all chunk-31 MMA reads done before H overwrites staging
        issueW2(0, 0);
        // epilogue: bias + CELU -> bf16 h planes
        #pragma unroll
        for (int mi = 0; mi < 4; mi++) {
            int r0 = mB + mi * 16 + gid;
            int r1 = r0 + 8;
            #pragma unroll
            for (int j = 0; j < 8; j++) {
                int c = nB + j * 8 + tig * 2;
                float bb0 = __ldg(b1g + c), bb1 = __ldg(b1g + c + 1);
                float v00 = celu01(acc[mi][j][0] + bb0);
                float v01 = celu01(acc[mi][j][1] + bb1);
                float v10 = celu01(acc[mi][j][2] + bb0);
                float v11 = celu01(acc[mi][j][3] + bb1);
                uint32_t h0 = cvt2(v00, v01);
                uint32_t l0 = cvt2(v00 - lo16f(h0), v01 - hi16f(h0));
                uint32_t h1 = cvt2(v10, v11);
                uint32_t l1 = cvt2(v10 - lo16f(h1), v11 - hi16f(h1));
                *(uint32_t*)(smc + HH + (r0 * 264 + c) * 2) = h0;
                *(uint32_t*)(smc + HL + (r0 * 264 + c) * 2) = l0;
                *(uint32_t*)(smc + HH + (r1 * 264 + c) * 2) = h1;
                *(uint32_t*)(smc + HL + (r1 * 264 + c) * 2) = l1;
            }
        }
    }

    // ==================== Layer 2: [128 x 256] @ [256 x 192] ====================
    {
        const int nB = wn * 48;
        float acc[4][6][4];
        #pragma unroll
        for (int mi = 0; mi < 4; mi++)
            #pragma unroll
            for (int j = 0; j < 6; j++)
                #pragma unroll
                for (int q = 0; q < 4; q++) acc[mi][j][q] = 0.f;

        for (int kc = 0; kc < NC2; ++kc) {
            if (kc + 1 < NC2) { issueW2(kc + 1, (kc + 1) & 1); CP_WAIT1(); }
            else              { CP_WAIT0(); }
            __syncthreads();
            const int b = kc & 1;
            #pragma unroll
            for (int ks = 0; ks < 2; ++ks) {
                const int kg0 = kc * 32 + ks * 16;
                uint32_t AH[4][4], AL[4][4];
                #pragma unroll
                for (int mi = 0; mi < 4; mi++) {
                    uint32_t aaddr = smem_base + HH
                                   + ((mB + mi * 16 + amrow) * 264 + kg0 + akoff) * 2;
                    ldm4(AH[mi], aaddr);
                    ldm4(AL[mi], aaddr + 67584);
                }
                #pragma unroll
                for (int jp = 0; jp < 3; ++jp) {
                    uint32_t baddr = smem_base + WPL(b, 0)
                                   + ((nB + jp * 16 + bnrow) * 40 + ks * 16 + bkoff) * 2;
                    uint32_t BH[4], BL[4];
                    ldm4(BH, baddr);
                    ldm4(BL, baddr + 15360);
                    #pragma unroll
                    for (int mi = 0; mi < 4; mi++) {
                        mma16(acc[mi][2 * jp],     AH[mi], BH);
                        mma16(acc[mi][2 * jp + 1], AH[mi], BH + 2);
                    }
                    #pragma unroll
                    for (int mi = 0; mi < 4; mi++) {
                        mma16(acc[mi][2 * jp],     AL[mi], BH);
                        mma16(acc[mi][2 * jp + 1], AL[mi], BH + 2);
                    }
                    #pragma unroll
                    for (int mi = 0; mi < 4; mi++) {
                        mma16(acc[mi][2 * jp],     AH[mi], BL);
                        mma16(acc[mi][2 * jp + 1], AH[mi], BL + 2);
                    }
                }
            }
            __syncthreads();
        }
        issueW3(0, 0);
        #pragma unroll
        for (int mi = 0; mi < 4; mi++) {
            int r0 = mB + mi * 16 + gid;
            int r1 = r0 + 8;
            #pragma unroll
            for (int j = 0; j < 6; j++) {
                int c = nB + j * 8 + tig * 2;
                float bb0 = __ldg(b2g + c), bb1 = __ldg(b2g + c + 1);
                float v00 = celu01(acc[mi][j][0] + bb0);
                float v01 = celu01(acc[mi][j][1] + bb1);
                float v10 = celu01(acc[mi][j][2] + bb0);
                float v11 = celu01(acc[mi][j][3] + bb1);
                uint32_t h0 = cvt2(v00, v01);
                uint32_t l0 = cvt2(v00 - lo16f(h0), v01 - hi16f(h0));
                uint32_t h1 = cvt2(v10, v11);
                uint32_t l1 = cvt2(v10 - lo16f(h1), v11 - hi16f(h1));
                *(uint32_t*)(smc + HH + (r0 * 264 + c) * 2) = h0;
                *(uint32_t*)(smc + HL + (r0 * 264 + c) * 2) = l0;
                *(uint32_t*)(smc + HH + (r1 * 264 + c) * 2) = h1;
                *(uint32_t*)(smc + HL + (r1 * 264 + c) * 2) = l1;
            }
        }
    }

    // ==================== Layer 3: [128 x 192] @ [192 x 160] ====================
    float energy = 0.f;
    {
        const int nB = wn * 40;
        float acc[4][5][4];
        #pragma unroll
        for (int mi = 0; mi < 4; mi++)
            #pragma unroll
            for (int j = 0; j < 5; j++)
                #pragma unroll
                for (int q = 0; q < 4; q++) acc[mi][j][q] = 0.f;

        for (int kc = 0; kc < NC3; ++kc) {
            if (kc + 1 < NC3) { issueW3(kc + 1, (kc + 1) & 1); CP_WAIT1(); }
            else              { CP_WAIT0(); }
            __syncthreads();
            const int b = kc & 1;
            #pragma unroll
            for (int ks = 0; ks < 2; ++ks) {
                const int kg0 = kc * 32 + ks * 16;
                uint32_t AH[4][4], AL[4][4];
                #pragma unroll
                for (int mi = 0; mi < 4; mi++) {
                    uint32_t aaddr = smem_base + HH
                                   + ((mB + mi * 16 + amrow) * 264 + kg0 + akoff) * 2;
                    ldm4(AH[mi], aaddr);
                    ldm4(AL[mi], aaddr + 67584);
                }
                #pragma unroll
                for (int jp = 0; jp < 2; ++jp) {
                    uint32_t baddr = smem_base + WPL(b, 0)
                                   + ((nB + jp * 16 + bnrow) * 40 + ks * 16 + bkoff) * 2;
                    uint32_t BH[4], BL[4];
                    ldm4(BH, baddr);
                    ldm4(BL, baddr + 15360);
                    #pragma unroll
                    for (int mi = 0; mi < 4; mi++) {
                        mma16(acc[mi][2 * jp],     AH[mi], BH);
                        mma16(acc[mi][2 * jp + 1], AH[mi], BH + 2);
                    }
                    #pragma unroll
                    for (int mi = 0; mi < 4; mi++) {
                        mma16(acc[mi][2 * jp],     AL[mi], BH);
                        mma16(acc[mi][2 * jp + 1], AL[mi], BH + 2);
                    }
                    #pragma unroll
                    for (int mi = 0; mi < 4; mi++) {
                        mma16(acc[mi][2 * jp],     AH[mi], BL);
                        mma16(acc[mi][2 * jp + 1], AH[mi], BL + 2);
                    }
                }
                {   // j = 4 (single octet) via ldmatrix.x2
                    uint32_t baddr = smem_base + WPL(b, 0)
                                   + ((nB + 32 + (lane & 7)) * 40 + ks * 16 + bkoff) * 2;
                    uint32_t BH[2], BL[2];
                    ldm2(BH, baddr);
                    ldm2(BL, baddr + 15360);
                    #pragma unroll
                    for (int mi = 0; mi < 4; mi++) mma16(acc[mi][4], AH[mi], BH);
                    #pragma unroll
                    for (int mi = 0; mi < 4; mi++) mma16(acc[mi][4], AL[mi], BH);
                    #pragma unroll
                    for (int mi = 0; mi < 4; mi++) mma16(acc[mi][4], AH[mi], BL);
                }
            }
            __syncthreads();
        }
        // epilogue: bias + CELU, dot with w4, row-masked
        #pragma unroll
        for (int mi = 0; mi < 4; mi++) {
            int r0 = mB + mi * 16 + gid;
            int r1 = r0 + 8;
            #pragma unroll
            for (int j = 0; j < 5; j++) {
                int n = nB + j * 8 + tig * 2;
                float bb0 = __ldg(b3g + n), bb1 = __ldg(b3g + n + 1);
                float w0  = __ldg(w4g + n), w1  = __ldg(w4g + n + 1);
                if (r0 < valid)
                    energy += celu01(acc[mi][j][0] + bb0) * w0
                            + celu01(acc[mi][j][1] + bb1) * w1;
                if (r1 < valid)
                    energy += celu01(acc[mi][j][2] + bb0) * w0
                            + celu01(acc[mi][j][3] + bb1) * w1;
            }
        }
    }

    red[tid] = energy;
    __syncthreads();
    #pragma unroll
    for (int st = 128; st > 0; st >>= 1) {
        if (tid < st) red[tid] += red[tid + st];
        __syncthreads();
    }
    if (tid == 0) {
        atomicAdd(&g_scratch, (double)(red[0] + (float)valid * B4[se]));
        __threadfence();
        int done = atomicAdd(&g_done, 1);
        if (done == NBLOCKS - 1)
            out[0] = (float)(g_scratch * (1.0 / ENS));
    }
}

extern "C" void kernel_launch(void* const* d_in, const int* in_sizes, int n_in,
                              void* d_out, int out_size)
{
    // Identify inputs by element count (robust to metadata ordering).
    const float *aev = 0, *W1 = 0, *B1 = 0, *W2 = 0, *B2 = 0,
                *W3 = 0, *B3 = 0, *W4 = 0, *B4 = 0;
    const int *idx = 0;
    int n5120 = 0, n50000 = 0;
    for (int i = 0; i < n_in; ++i) {
        switch (in_sizes[i]) {
            case 50400000: aev = (const float*)d_in[i]; break;
            case 8257536:  W1  = (const float*)d_in[i]; break;
            case 8192:     B1  = (const float*)d_in[i]; break;
            case 1572864:  W2  = (const float*)d_in[i]; break;
            case 6144:     B2  = (const float*)d_in[i]; break;
            case 983040:   W3  = (const float*)d_in[i]; break;
            case 5120:
                if (n5120++ == 0) B3 = (const float*)d_in[i];
                else              W4 = (const float*)d_in[i];
                break;
            case 32:       B4  = (const float*)d_in[i]; break;
            case 50000:
                if (n50000++ == 0) { /* species (unused) */ }
                else idx = (const int*)d_in[i];
                break;
            default: break;
        }
    }

    cudaFuncSetAttribute(ani_main,
                         cudaFuncAttributeMaxDynamicSharedMemorySize, SMEM_BYTES);

    prep_all<<<(int)((T_ALL + 255) / 256), 256>>>(aev, W1, W2, W3);

    dim3 grid(ENS, NTILES, NSPECIES);
    ani_main<<<grid, 256, SMEM_BYTES>>>(B1, B2, B3, W4, B4, idx, (float*)d_out);
}

// round 9
// speedup vs baseline: 1.0054x; 1.0054x over previous
#include <cuda_runtime.h>
#include <cstdint>

// ---------------- problem constants ----------------
#define NS_PER   12500
#define AEVD     1008
#define KPAD1    1024
#define D1       256
#define D2       192
#define D3       160
#define ENS      8
#define NSPECIES 4
#define TM       64
#define NTILES   196
#define NATOM    50000
#define NSE      32
#define NBLOCKS  (ENS * NTILES * NSPECIES)   // 6272

#define NC1 32    // KPAD1/32 (K=32 chunks)
#define NC2 16    // D1/16   (K=16 chunks)
#define NC3 12    // D2/16

// ---------------- persistent bf16 plane scratch ----------------
__device__ uint16_t g_aevH[(size_t)NATOM * KPAD1];
__device__ uint16_t g_aevL[(size_t)NATOM * KPAD1];
__device__ uint16_t g_w1H[(size_t)NSE * D1 * KPAD1];
__device__ uint16_t g_w1L[(size_t)NSE * D1 * KPAD1];
__device__ uint16_t g_w2H[(size_t)NSE * D2 * D1];
__device__ uint16_t g_w2L[(size_t)NSE * D2 * D1];
__device__ uint16_t g_w3H[(size_t)NSE * D3 * D2];
__device__ uint16_t g_w3L[(size_t)NSE * D3 * D2];
__device__ double g_scratch;
__device__ int    g_done;

// ---------------- smem layout (bytes) ----------------
#define RI_OFF   0                           // 64 ints
#define RED_OFF  256                         // 128 floats
#define PL       1024
// L1 staging: 2 stages, each [Ah 5120][Al 5120][Bh 20480][Bl 20480] = 51200
#define APL(st,p) (PL + (st)*51200 + (p)*5120)
#define BPL(st,p) (PL + (st)*51200 + 10240 + (p)*20480)
// h planes overwrite staging after L1: [64][264] bf16 per plane
#define HH       PL
#define HL       (PL + 33792)
// W2/W3 staging (K=16 chunks, stride 24 elems = 48B rows): plane 192*24*2 = 9216
#define WPL(b,p) (PL + 67584 + (b)*18432 + (p)*9216)
#define SMEM_BYTES (PL + 67584 + 36864)      // 105472  (>= PL+2*51200 = 103424)

// ---------------- helpers ----------------
__device__ __forceinline__ uint32_t cvt2(float v0, float v1) {  // v0->lo16, v1->hi16
    uint32_t r;
    asm("cvt.rn.bf16x2.f32 %0, %1, %2;" : "=r"(r) : "f"(v1), "f"(v0));
    return r;
}
__device__ __forceinline__ float lo16f(uint32_t h) { return __uint_as_float(h << 16); }
__device__ __forceinline__ float hi16f(uint32_t h) { return __uint_as_float(h & 0xFFFF0000u); }

__device__ __forceinline__ float celu01(float x) {
    return x > 0.f ? x : 0.1f * (__expf(x * 10.f) - 1.f);
}

__device__ __forceinline__ void mma16(float d[4], const uint32_t a[4], const uint32_t b[2]) {
    asm volatile(
        "mma.sync.aligned.m16n8k16.row.col.f32.bf16.bf16.f32 "
        "{%0,%1,%2,%3},{%4,%5,%6,%7},{%8,%9},{%0,%1,%2,%3};\n"
        : "+f"(d[0]), "+f"(d[1]), "+f"(d[2]), "+f"(d[3])
        : "r"(a[0]), "r"(a[1]), "r"(a[2]), "r"(a[3]), "r"(b[0]), "r"(b[1]));
}

__device__ __forceinline__ void ldm4(uint32_t* r, uint32_t addr) {
    asm volatile("ldmatrix.sync.aligned.m8n8.x4.shared.b16 {%0,%1,%2,%3}, [%4];"
                 : "=r"(r[0]), "=r"(r[1]), "=r"(r[2]), "=r"(r[3]) : "r"(addr));
}
__device__ __forceinline__ void ldm2(uint32_t* r, uint32_t addr) {
    asm volatile("ldmatrix.sync.aligned.m8n8.x2.shared.b16 {%0,%1}, [%2];"
                 : "=r"(r[0]), "=r"(r[1]) : "r"(addr));
}

__device__ __forceinline__ void cp16(uint32_t dst, const void* src, int szbytes) {
    asm volatile("cp.async.ca.shared.global [%0], [%1], 16, %2;\n"
                 :: "r"(dst), "l"(src), "r"(szbytes));
}
#define CP_COMMIT()  asm volatile("cp.async.commit_group;\n" ::)
#define CP_WAIT1()   asm volatile("cp.async.wait_group 1;\n" ::)
#define CP_WAIT0()   asm volatile("cp.async.wait_group 0;\n" ::)

// ---------------- merged pre-pass (also resets accumulators) ----------------
#define T_AEV ((long)NATOM * (KPAD1 / 2))
#define T_W1  ((long)NSE * D1 * (KPAD1 / 2))
#define T_W2  ((long)NSE * D2 * (D1 / 2))
#define T_W3  ((long)NSE * D3 * (D2 / 2))
#define T_ALL (T_AEV + T_W1 + T_W2 + T_W3)

__global__ void prep_all(const float* __restrict__ aev, const float* __restrict__ W1,
                         const float* __restrict__ W2, const float* __restrict__ W3)
{
    long t = (long)blockIdx.x * 256 + threadIdx.x;
    if (t == 0) { g_scratch = 0.0; g_done = 0; }
    if (t >= T_ALL) return;

    if (t < T_AEV) {
        long a  = t / (KPAD1 / 2);
        int  kp = (int)(t - a * (KPAD1 / 2));
        int  k  = 2 * kp;
        float v0 = (k     < AEVD) ? aev[(size_t)a * AEVD + k]     : 0.f;
        float v1 = (k + 1 < AEVD) ? aev[(size_t)a * AEVD + k + 1] : 0.f;
        uint32_t h = cvt2(v0, v1);
        uint32_t l = cvt2(v0 - lo16f(h), v1 - hi16f(h));
        ((uint32_t*)g_aevH)[t] = h;
        ((uint32_t*)g_aevL)[t] = l;
        return;
    }
    const float* W; uint16_t *dH, *dL; int K, N, Kpad; long u;
    if (t < T_AEV + T_W1)      { u = t - T_AEV;        W = W1; dH = g_w1H; dL = g_w1L; K = AEVD; N = D1; Kpad = KPAD1; }
    else if (t < T_AEV + T_W1 + T_W2) { u = t - T_AEV - T_W1; W = W2; dH = g_w2H; dL = g_w2L; K = D1; N = D2; Kpad = D1; }
    else                       { u = t - T_AEV - T_W1 - T_W2; W = W3; dH = g_w3H; dL = g_w3L; K = D2; N = D3; Kpad = D2; }
    int n  = (int)(u % N);
    long r = u / N;
    int kp = (int)(r % (Kpad / 2));
    int se = (int)(r / (Kpad / 2));
    int k  = 2 * kp;
    float v0 = (k     < K) ? W[((size_t)se * K + k) * N + n]     : 0.f;
    float v1 = (k + 1 < K) ? W[((size_t)se * K + k + 1) * N + n] : 0.f;
    uint32_t h = cvt2(v0, v1);
    uint32_t l = cvt2(v0 - lo16f(h), v1 - hi16f(h));
    size_t di = ((size_t)se * N + n) * (Kpad / 2) + kp;
    ((uint32_t*)dH)[di] = h;
    ((uint32_t*)dL)[di] = l;
}

// ---------------- main fused kernel: 128 threads, 2 CTAs/SM ----------------
__global__ void __launch_bounds__(128, 2)
ani_main(const float* __restrict__ B1, const float* __restrict__ B2,
         const float* __restrict__ B3, const float* __restrict__ W4,
         const float* __restrict__ B4, const int* __restrict__ idx,
         float* __restrict__ out)
{
    extern __shared__ char smc[];
    const uint32_t smem_base = (uint32_t)__cvta_generic_to_shared(smc);
    int*   rowIdx = (int*)(smc + RI_OFF);
    float* red    = (float*)(smc + RED_OFF);

    const int e    = blockIdx.x;
    const int tile = blockIdx.y;
    const int s    = blockIdx.z;
    const int se   = s * ENS + e;

    const int tid  = threadIdx.x;
    const int lane = tid & 31;
    const int wn   = tid >> 5;     // 0..3 : N columns; all warps cover full M=64
    const int gid  = lane >> 2;
    const int tig  = lane & 3;

    const int amrow = (lane & 7) + (lane & 8);
    const int akoff = (lane & 16) >> 1;
    const int bnrow = (lane & 7) + ((lane & 16) >> 1);
    const int bkoff = lane & 8;

    const int tileBase = tile * TM;
    const int valid    = min(TM, NS_PER - tileBase);

    if (tid < TM)
        rowIdx[tid] = (tid < valid) ? idx[s * NS_PER + tileBase + tid] : -1;
    __syncthreads();

    const float* b1g = B1 + (size_t)se * D1;
    const float* b2g = B2 + (size_t)se * D2;
    const float* b3g = B3 + (size_t)se * D3;
    const float* w4g = W4 + (size_t)se * D3;

    // ---------------- cp.async issue helpers (128 threads) ----------------
    auto issueA1 = [&](int kc, int st) {
        #pragma unroll
        for (int it = 0; it < 4; ++it) {
            int t = tid + it * 128;          // 0..511 (2 planes x 64 rows x 4 segs)
            int p   = t >> 8;
            int rem = t & 255;
            int r   = rem >> 2;
            int seg = rem & 3;
            int g   = rowIdx[r];
            const uint16_t* base = p ? g_aevL : g_aevH;
            const uint16_t* src  = base + ((size_t)(g < 0 ? 0 : g) * KPAD1 + kc * 32 + seg * 8);
            cp16(smem_base + APL(st, p) + (r * 40 + seg * 8) * 2, src, g >= 0 ? 16 : 0);
        }
    };
    auto issueB1 = [&](int kc, int st) {
        #pragma unroll
        for (int it = 0; it < 16; ++it) {
            int t = tid + it * 128;          // 0..2047 (2 planes x 256 n x 4 segs)
            int p   = t >> 10;
            int rem = t & 1023;
            int n   = rem >> 2;
            int seg = rem & 3;
            const uint16_t* base = p ? g_w1L : g_w1H;
            cp16(smem_base + BPL(st, p) + (n * 40 + seg * 8) * 2,
                 base + ((size_t)(se * D1 + n) * KPAD1 + kc * 32 + seg * 8), 16);
        }
        CP_COMMIT();
    };
    auto issueW2 = [&](int kc, int b) {
        #pragma unroll
        for (int it = 0; it < 6; ++it) {
            int t = tid + it * 128;          // 0..767 (2 planes x 192 n x 2 segs)
            int p   = t >= 384;
            int rem = t - p * 384;
            int n   = rem >> 1;
            int seg = rem & 1;
            const uint16_t* base = p ? g_w2L : g_w2H;
            cp16(smem_base + WPL(b, p) + (n * 24 + seg * 8) * 2,
                 base + ((size_t)(se * D2 + n) * D1 + kc * 16 + seg * 8), 16);
        }
        CP_COMMIT();
    };
    auto issueW3 = [&](int kc, int b) {
        #pragma unroll
        for (int it = 0; it < 5; ++it) {
            int t = tid + it * 128;          // 0..639 (2 planes x 160 n x 2 segs)
            int p   = t >= 320;
            int rem = t - p * 320;
            int n   = rem >> 1;
            int seg = rem & 1;
            const uint16_t* base = p ? g_w3L : g_w3H;
            cp16(smem_base + WPL(b, p) + (n * 24 + seg * 8) * 2,
                 base + ((size_t)(se * D3 + n) * D2 + kc * 16 + seg * 8), 16);
        }
        CP_COMMIT();
    };

    // ==================== Layer 1: [64 x 1024] @ [1024 x 256] ====================
    {
        const int nB = wn * 64;
        float acc[4][8][4];
        #pragma unroll
        for (int mi = 0; mi < 4; mi++)
            #pragma unroll
            for (int j = 0; j < 8; j++)
                #pragma unroll
                for (int q = 0; q < 4; q++) acc[mi][j][q] = 0.f;

        issueA1(0, 0); issueB1(0, 0);
        for (int kc = 0; kc < NC1; ++kc) {
            const int st = kc & 1;
            if (kc + 1 < NC1) { issueA1(kc + 1, st ^ 1); issueB1(kc + 1, st ^ 1); CP_WAIT1(); }
            else              { CP_WAIT0(); }
            __syncthreads();
            #pragma unroll
            for (int ks = 0; ks < 2; ++ks) {
                const int k0 = ks * 16;
                uint32_t AH[4][4], AL[4][4];
                #pragma unroll
                for (int mi = 0; mi < 4; mi++) {
                    uint32_t aaddr = smem_base + APL(st, 0)
                                   + ((mi * 16 + amrow) * 40 + k0 + akoff) * 2;
                    ldm4(AH[mi], aaddr);
                    ldm4(AL[mi], aaddr + 5120);
                }
                #pragma unroll
                for (int jp = 0; jp < 4; ++jp) {
                    uint32_t baddr = smem_base + BPL(st, 0)
                                   + ((nB + jp * 16 + bnrow) * 40 + k0 + bkoff) * 2;
                    uint32_t BH[4], BL[4];
                    ldm4(BH, baddr);
                    ldm4(BL, baddr + 20480);
                    #pragma unroll
                    for (int mi = 0; mi < 4; mi++) {
                        mma16(acc[mi][2 * jp],     AH[mi], BH);
                        mma16(acc[mi][2 * jp],     AL[mi], BH);
                        mma16(acc[mi][2 * jp],     AH[mi], BL);
                        mma16(acc[mi][2 * jp + 1], AH[mi], BH + 2);
                        mma16(acc[mi][2 * jp + 1], AL[mi], BH + 2);
                        mma16(acc[mi][2 * jp + 1], AH[mi], BL + 2);
                    }
                }
            }
            __syncthreads();
        }
        issueW2(0, 0);
        // epilogue: bias + CELU -> bf16 h planes (overwrites L1 staging)
        #pragma unroll
        for (int mi = 0; mi < 4; mi++) {
            int r0 = mi * 16 + gid;
            int r1 = r0 + 8;
            #pragma unroll
            for (int j = 0; j < 8; j++) {
                int c = nB + j * 8 + tig * 2;
                float bb0 = __ldg(b1g + c), bb1 = __ldg(b1g + c + 1);
                float v00 = celu01(acc[mi][j][0] + bb0);
                float v01 = celu01(acc[mi][j][1] + bb1);
                float v10 = celu01(acc[mi][j][2] + bb0);
                float v11 = celu01(acc[mi][j][3] + bb1);
                uint32_t h0 = cvt2(v00, v01);
                uint32_t l0 = cvt2(v00 - lo16f(h0), v01 - hi16f(h0));
                uint32_t h1 = cvt2(v10, v11);
                uint32_t l1 = cvt2(v10 - lo16f(h1), v11 - hi16f(h1));
                *(uint32_t*)(smc + HH + (r0 * 264 + c) * 2) = h0;
                *(uint32_t*)(smc + HL + (r0 * 264 + c) * 2) = l0;
                *(uint32_t*)(smc + HH + (r1 * 264 + c) * 2) = h1;
                *(uint32_t*)(smc + HL + (r1 * 264 + c) * 2) = l1;
            }
        }
    }

    // ==================== Layer 2: [64 x 256] @ [256 x 192], K=16 chunks ====================
    {
        const int nB = wn * 48;
        float acc[4][6][4];
        #pragma unroll
        for (int mi = 0; mi < 4; mi++)
            #pragma unroll
            for (int j = 0; j < 6; j++)
                #pragma unroll
                for (int q = 0; q < 4; q++) acc[mi][j][q] = 0.f;

        for (int kc = 0; kc < NC2; ++kc) {
            if (kc + 1 < NC2) { issueW2(kc + 1, (kc + 1) & 1); CP_WAIT1(); }
            else              { CP_WAIT0(); }
            __syncthreads();
            const int b = kc & 1;
            const int kg0 = kc * 16;
            uint32_t AH[4][4], AL[4][4];
            #pragma unroll
            for (int mi = 0; mi < 4; mi++) {
                uint32_t aaddr = smem_base + HH
                               + ((mi * 16 + amrow) * 264 + kg0 + akoff) * 2;
                ldm4(AH[mi], aaddr);
                ldm4(AL[mi], aaddr + 33792);
            }
            #pragma unroll
            for (int jp = 0; jp < 3; ++jp) {
                uint32_t baddr = smem_base + WPL(b, 0)
                               + ((nB + jp * 16 + bnrow) * 24 + bkoff) * 2;
                uint32_t BH[4], BL[4];
                ldm4(BH, baddr);
                ldm4(BL, baddr + 9216);
                #pragma unroll
                for (int mi = 0; mi < 4; mi++) {
                    mma16(acc[mi][2 * jp],     AH[mi], BH);
                    mma16(acc[mi][2 * jp],     AL[mi], BH);
                    mma16(acc[mi][2 * jp],     AH[mi], BL);
                    mma16(acc[mi][2 * jp + 1], AH[mi], BH + 2);
                    mma16(acc[mi][2 * jp + 1], AL[mi], BH + 2);
                    mma16(acc[mi][2 * jp + 1], AH[mi], BL + 2);
                }
            }
            __syncthreads();
        }
        issueW3(0, 0);
        // epilogue -> h2 planes (cols 0..191)
        #pragma unroll
        for (int mi = 0; mi < 4; mi++) {
            int r0 = mi * 16 + gid;
            int r1 = r0 + 8;
            #pragma unroll
            for (int j = 0; j < 6; j++) {
                int c = nB + j * 8 + tig * 2;
                float bb0 = __ldg(b2g + c), bb1 = __ldg(b2g + c + 1);
                float v00 = celu01(acc[mi][j][0] + bb0);
                float v01 = celu01(acc[mi][j][1] + bb1);
                float v10 = celu01(acc[mi][j][2] + bb0);
                float v11 = celu01(acc[mi][j][3] + bb1);
                uint32_t h0 = cvt2(v00, v01);
                uint32_t l0 = cvt2(v00 - lo16f(h0), v01 - hi16f(h0));
                uint32_t h1 = cvt2(v10, v11);
                uint32_t l1 = cvt2(v10 - lo16f(h1), v11 - hi16f(h1));
                *(uint32_t*)(smc + HH + (r0 * 264 + c) * 2) = h0;
                *(uint32_t*)(smc + HL + (r0 * 264 + c) * 2) = l0;
                *(uint32_t*)(smc + HH + (r1 * 264 + c) * 2) = h1;
                *(uint32_t*)(smc + HL + (r1 * 264 + c) * 2) = l1;
            }
        }
    }

    // ==================== Layer 3: [64 x 192] @ [192 x 160], K=16 chunks ====================
    float energy = 0.f;
    {
        const int nB = wn * 40;
        float acc[4][5][4];
        #pragma unroll
        for (int mi = 0; mi < 4; mi++)
            #pragma unroll
            for (int j = 0; j < 5; j++)
                #pragma unroll
                for (int q = 0; q < 4; q++) acc[mi][j][q] = 0.f;

        for (int kc = 0; kc < NC3; ++kc) {
            if (kc + 1 < NC3) { issueW3(kc + 1, (kc + 1) & 1); CP_WAIT1(); }
            else              { CP_WAIT0(); }
            __syncthreads();
            const int b = kc & 1;
            const int kg0 = kc * 16;
            uint32_t AH[4][4], AL[4][4];
            #pragma unroll
            for (int mi = 0; mi < 4; mi++) {
                uint32_t aaddr = smem_base + HH
                               + ((mi * 16 + amrow) * 264 + kg0 + akoff) * 2;
                ldm4(AH[mi], aaddr);
                ldm4(AL[mi], aaddr + 33792);
            }
            #pragma unroll
            for (int jp = 0; jp < 2; ++jp) {
                uint32_t baddr = smem_base + WPL(b, 0)
                               + ((nB + jp * 16 + bnrow) * 24 + bkoff) * 2;
                uint32_t BH[4], BL[4];
                ldm4(BH, baddr);
                ldm4(BL, baddr + 9216);
                #pragma unroll
                for (int mi = 0; mi < 4; mi++) {
                    mma16(acc[mi][2 * jp],     AH[mi], BH);
                    mma16(acc[mi][2 * jp],     AL[mi], BH);
                    mma16(acc[mi][2 * jp],     AH[mi], BL);
                    mma16(acc[mi][2 * jp + 1], AH[mi], BH + 2);
                    mma16(acc[mi][2 * jp + 1], AL[mi], BH + 2);
                    mma16(acc[mi][2 * jp + 1], AH[mi], BL + 2);
                }
            }
            {   // j = 4 (single octet) via ldmatrix.x2
                uint32_t baddr = smem_base + WPL(b, 0)
                               + ((nB + 32 + (lane & 7)) * 24 + bkoff) * 2;
                uint32_t BH[2], BL[2];
                ldm2(BH, baddr);
                ldm2(BL, baddr + 9216);
                #pragma unroll
                for (int mi = 0; mi < 4; mi++) {
                    mma16(acc[mi][4], AH[mi], BH);
                    mma16(acc[mi][4], AL[mi], BH);
                    mma16(acc[mi][4], AH[mi], BL);
                }
            }
            __syncthreads();
        }
        // epilogue: bias + CELU, dot with w4, row-masked
        #pragma unroll
        for (int mi = 0; mi < 4; mi++) {
            int r0 = mi * 16 + gid;
            int r1 = r0 + 8;
            #pragma unroll
            for (int j = 0; j < 5; j++) {
                int n = nB + j * 8 + tig * 2;
                float bb0 = __ldg(b3g + n), bb1 = __ldg(b3g + n + 1);
                float w0  = __ldg(w4g + n), w1  = __ldg(w4g + n + 1);
                if (r0 < valid)
                    energy += celu01(acc[mi][j][0] + bb0) * w0
                            + celu01(acc[mi][j][1] + bb1) * w1;
                if (r1 < valid)
                    energy += celu01(acc[mi][j][2] + bb0) * w0
                            + celu01(acc[mi][j][3] + bb1) * w1;
            }
        }
    }

    red[tid] = energy;
    __syncthreads();
    #pragma unroll
    for (int st = 64; st > 0; st >>= 1) {
        if (tid < st) red[tid] += red[tid + st];
        __syncthreads();
    }
    if (tid == 0) {
        atomicAdd(&g_scratch, (double)(red[0] + (float)valid * B4[se]));
        __threadfence();
        int done = atomicAdd(&g_done, 1);
        if (done == NBLOCKS - 1)
            out[0] = (float)(g_scratch * (1.0 / ENS));
    }
}

extern "C" void kernel_launch(void* const* d_in, const int* in_sizes, int n_in,
                              void* d_out, int out_size)
{
    // Identify inputs by element count (robust to metadata ordering).
    const float *aev = 0, *W1 = 0, *B1 = 0, *W2 = 0, *B2 = 0,
                *W3 = 0, *B3 = 0, *W4 = 0, *B4 = 0;
    const int *idx = 0;
    int n5120 = 0, n50000 = 0;
    for (int i = 0; i < n_in; ++i) {
        switch (in_sizes[i]) {
            case 50400000: aev = (const float*)d_in[i]; break;
            case 8257536:  W1  = (const float*)d_in[i]; break;
            case 8192:     B1  = (const float*)d_in[i]; break;
            case 1572864:  W2  = (const float*)d_in[i]; break;
            case 6144:     B2  = (const float*)d_in[i]; break;
            case 983040:   W3  = (const float*)d_in[i]; break;
            case 5120:
                if (n5120++ == 0) B3 = (const float*)d_in[i];
                else              W4 = (const float*)d_in[i];
                break;
            case 32:       B4  = (const float*)d_in[i]; break;
            case 50000:
                if (n50000++ == 0) { /* species (unused) */ }
                else idx = (const int*)d_in[i];
                break;
            default: break;
        }
    }

    cudaFuncSetAttribute(ani_main,
                         cudaFuncAttributeMaxDynamicSharedMemorySize, SMEM_BYTES);

    prep_all<<<(int)((T_ALL + 255) / 256), 256>>>(aev, W1, W2, W3);

    dim3 grid(ENS, NTILES, NSPECIES);
    ani_main<<<grid, 128, SMEM_BYTES>>>(B1, B2, B3, W4, B4, idx, (float*)d_out);
}

// round 10
// speedup vs baseline: 1.3395x; 1.3323x over previous
#include <cuda_runtime.h>
#include <cuda_fp16.h>
#include <cstdint>

// ---------------- problem constants ----------------
#define NS_PER   12500
#define AEVD     1008
#define KPAD1    1024
#define D1       256
#define D2       192
#define D3       160
#define ENS      8
#define NSPECIES 4
#define TM       128
#define NTILES   98
#define NATOM    50000
#define NSE      32
#define NBLOCKS  (ENS * NTILES * NSPECIES)   // 3136

#define NC1 32    // KPAD1/32
#define NC2 8     // D1/32
#define NC3 6     // D2/32

// ---------------- persistent plane scratch ----------------
// aev: fp16 hi/lo planes; W1: single fp16 plane; W2/W3: bf16 hi/lo planes.
__device__ uint16_t g_aevH[(size_t)NATOM * KPAD1];
__device__ uint16_t g_aevL[(size_t)NATOM * KPAD1];
__device__ uint16_t g_w1H[(size_t)NSE * D1 * KPAD1];
__device__ uint16_t g_w2H[(size_t)NSE * D2 * D1];
__device__ uint16_t g_w2L[(size_t)NSE * D2 * D1];
__device__ uint16_t g_w3H[(size_t)NSE * D3 * D2];
__device__ uint16_t g_w3L[(size_t)NSE * D3 * D2];
__device__ double g_scratch;
__device__ int    g_done;

// ---------------- smem layout (bytes) ----------------
#define RI_OFF   0                          // 128 ints
#define RED_OFF  512                        // 256 floats
#define PL       2048
// L1 staging: 2 stages, each [Ah 10240][Al 10240][Bh 20480] = 40960
#define APL(st,p) (PL + (st)*40960 + (p)*10240)
#define BPL(st)   (PL + (st)*40960 + 20480)
// h planes (bf16) overwrite staging after L1: [128][264] per plane
#define HH       PL
#define HL       (PL + 67584)
// W2/W3 2-stage staging after H region (stride 40, K=32 chunks)
#define WPL(b,p) (PL + 135168 + (b)*30720 + (p)*15360)
#define SMEM_BYTES (PL + 135168 + 61440)    // 198656

// ---------------- helpers ----------------
__device__ __forceinline__ uint32_t cvt2(float v0, float v1) {  // bf16x2: v0->lo, v1->hi
    uint32_t r;
    asm("cvt.rn.bf16x2.f32 %0, %1, %2;" : "=r"(r) : "f"(v1), "f"(v0));
    return r;
}
__device__ __forceinline__ uint32_t cvt2h(float v0, float v1) { // f16x2: v0->lo, v1->hi
    uint32_t r;
    asm("cvt.rn.f16x2.f32 %0, %1, %2;" : "=r"(r) : "f"(v1), "f"(v0));
    return r;
}
__device__ __forceinline__ float lo16f(uint32_t h) { return __uint_as_float(h << 16); }
__device__ __forceinline__ float hi16f(uint32_t h) { return __uint_as_float(h & 0xFFFF0000u); }

__device__ __forceinline__ float celu01(float x) {
    return x > 0.f ? x : 0.1f * (__expf(x * 10.f) - 1.f);
}

__device__ __forceinline__ void mma16(float d[4], const uint32_t a[4], const uint32_t b[2]) {
    asm volatile(
        "mma.sync.aligned.m16n8k16.row.col.f32.bf16.bf16.f32 "
        "{%0,%1,%2,%3},{%4,%5,%6,%7},{%8,%9},{%0,%1,%2,%3};\n"
        : "+f"(d[0]), "+f"(d[1]), "+f"(d[2]), "+f"(d[3])
        : "r"(a[0]), "r"(a[1]), "r"(a[2]), "r"(a[3]), "r"(b[0]), "r"(b[1]));
}
__device__ __forceinline__ void mma16h(float d[4], const uint32_t a[4], const uint32_t b[2]) {
    asm volatile(
        "mma.sync.aligned.m16n8k16.row.col.f32.f16.f16.f32 "
        "{%0,%1,%2,%3},{%4,%5,%6,%7},{%8,%9},{%0,%1,%2,%3};\n"
        : "+f"(d[0]), "+f"(d[1]), "+f"(d[2]), "+f"(d[3])
        : "r"(a[0]), "r"(a[1]), "r"(a[2]), "r"(a[3]), "r"(b[0]), "r"(b[1]));
}

__device__ __forceinline__ void ldm4(uint32_t* r, uint32_t addr) {
    asm volatile("ldmatrix.sync.aligned.m8n8.x4.shared.b16 {%0,%1,%2,%3}, [%4];"
                 : "=r"(r[0]), "=r"(r[1]), "=r"(r[2]), "=r"(r[3]) : "r"(addr));
}
__device__ __forceinline__ void ldm2(uint32_t* r, uint32_t addr) {
    asm volatile("ldmatrix.sync.aligned.m8n8.x2.shared.b16 {%0,%1}, [%2];"
                 : "=r"(r[0]), "=r"(r[1]) : "r"(addr));
}

__device__ __forceinline__ void cp16(uint32_t dst, const void* src, int szbytes) {
    asm volatile("cp.async.ca.shared.global [%0], [%1], 16, %2;\n"
                 :: "r"(dst), "l"(src), "r"(szbytes));
}
#define CP_COMMIT()  asm volatile("cp.async.commit_group;\n" ::)
#define CP_WAIT1()   asm volatile("cp.async.wait_group 1;\n" ::)
#define CP_WAIT0()   asm volatile("cp.async.wait_group 0;\n" ::)

// ---------------- merged pre-pass ----------------
#define T_AEV ((long)NATOM * (KPAD1 / 2))
#define T_W1  ((long)NSE * D1 * (KPAD1 / 2))
#define T_W2  ((long)NSE * D2 * (D1 / 2))
#define T_W3  ((long)NSE * D3 * (D2 / 2))
#define T_ALL (T_AEV + T_W1 + T_W2 + T_W3)

__global__ void prep_all(const float* __restrict__ aev, const float* __restrict__ W1,
                         const float* __restrict__ W2, const float* __restrict__ W3)
{
    long t = (long)blockIdx.x * 256 + threadIdx.x;
    if (t == 0) { g_scratch = 0.0; g_done = 0; }
    if (t >= T_ALL) return;

    if (t < T_AEV) {
        // aev -> fp16 hi/lo planes
        long a  = t / (KPAD1 / 2);
        int  kp = (int)(t - a * (KPAD1 / 2));
        int  k  = 2 * kp;
        float v0 = (k     < AEVD) ? aev[(size_t)a * AEVD + k]     : 0.f;
        float v1 = (k + 1 < AEVD) ? aev[(size_t)a * AEVD + k + 1] : 0.f;
        uint32_t h = cvt2h(v0, v1);
        __half2 hh = *reinterpret_cast<__half2*>(&h);
        uint32_t l = cvt2h(v0 - __half2float(hh.x), v1 - __half2float(hh.y));
        ((uint32_t*)g_aevH)[t] = h;
        ((uint32_t*)g_aevL)[t] = l;
        return;
    }
    if (t < T_AEV + T_W1) {
        // W1 -> single fp16 plane, transposed [se][n][kpad]
        long u = t - T_AEV;
        int n  = (int)(u % D1);
        long r = u / D1;
        int kp = (int)(r % (KPAD1 / 2));
        int se = (int)(r / (KPAD1 / 2));
        int k  = 2 * kp;
        float v0 = (k     < AEVD) ? W1[((size_t)se * AEVD + k) * D1 + n]     : 0.f;
        float v1 = (k + 1 < AEVD) ? W1[((size_t)se * AEVD + k + 1) * D1 + n] : 0.f;
        size_t di = ((size_t)se * D1 + n) * (KPAD1 / 2) + kp;
        ((uint32_t*)g_w1H)[di] = cvt2h(v0, v1);
        return;
    }
    // W2 / W3 -> bf16 hi/lo planes (transposed)
    const float* W; uint16_t *dH, *dL; int K, N; long u;
    if (t < T_AEV + T_W1 + T_W2) { u = t - T_AEV - T_W1;        W = W2; dH = g_w2H; dL = g_w2L; K = D1; N = D2; }
    else                         { u = t - T_AEV - T_W1 - T_W2; W = W3; dH = g_w3H; dL = g_w3L; K = D2; N = D3; }
    int n  = (int)(u % N);
    long r = u / N;
    int kp = (int)(r % (K / 2));
    int se = (int)(r / (K / 2));
    int k  = 2 * kp;
    float v0 = W[((size_t)se * K + k) * N + n];
    float v1 = W[((size_t)se * K + k + 1) * N + n];
    uint32_t h = cvt2(v0, v1);
    uint32_t l = cvt2(v0 - lo16f(h), v1 - hi16f(h));
    size_t di = ((size_t)se * N + n) * (K / 2) + kp;
    ((uint32_t*)dH)[di] = h;
    ((uint32_t*)dL)[di] = l;
}

// ---------------- main fused kernel (256 threads, 2x4 warps; R6 structure) ----------------
__global__ void __launch_bounds__(256, 1)
ani_main(const float* __restrict__ B1, const float* __restrict__ B2,
         const float* __restrict__ B3, const float* __restrict__ W4,
         const float* __restrict__ B4, const int* __restrict__ idx,
         float* __restrict__ out)
{
    extern __shared__ char smc[];
    const uint32_t smem_base = (uint32_t)__cvta_generic_to_shared(smc);
    int*   rowIdx = (int*)(smc + RI_OFF);
    float* red    = (float*)(smc + RED_OFF);

    const int e    = blockIdx.x;
    const int tile = blockIdx.y;
    const int s    = blockIdx.z;
    const int se   = s * ENS + e;

    const int tid  = threadIdx.x;
    const int lane = tid & 31;
    const int warp = tid >> 5;
    const int gid  = lane >> 2;
    const int tig  = lane & 3;
    const int wm   = warp & 1;
    const int wn   = warp >> 1;     // 0..3
    const int mB   = wm * 64;

    const int amrow = (lane & 7) + (lane & 8);
    const int akoff = (lane & 16) >> 1;
    const int bnrow = (lane & 7) + ((lane & 16) >> 1);
    const int bkoff = lane & 8;

    const int tileBase = tile * TM;
    const int valid    = min(TM, NS_PER - tileBase);

    if (tid < TM)
        rowIdx[tid] = (tid < valid) ? idx[s * NS_PER + tileBase + tid] : -1;
    __syncthreads();

    const float* b1g = B1 + (size_t)se * D1;
    const float* b2g = B2 + (size_t)se * D2;
    const float* b3g = B3 + (size_t)se * D3;
    const float* w4g = W4 + (size_t)se * D3;

    // ---------------- cp.async issue helpers ----------------
    auto issueA1 = [&](int kc, int st) {
        #pragma unroll
        for (int it = 0; it < 4; ++it) {
            int t = tid + it * 256;          // 0..1023 : 2 planes x 128 rows x 4 segs
            int p   = t >> 9;
            int rem = t & 511;
            int r   = rem >> 2;
            int seg = rem & 3;
            int g   = rowIdx[r];
            const uint16_t* base = p ? g_aevL : g_aevH;
            const uint16_t* src  = base + ((size_t)(g < 0 ? 0 : g) * KPAD1 + kc * 32 + seg * 8);
            cp16(smem_base + APL(st, p) + (r * 40 + seg * 8) * 2, src, g >= 0 ? 16 : 0);
        }
    };
    auto issueB1 = [&](int kc, int st) {
        #pragma unroll
        for (int it = 0; it < 4; ++it) {
            int t = tid + it * 256;          // 0..1023 : 256 n x 4 segs (single fp16 plane)
            int n   = t >> 2;
            int seg = t & 3;
            cp16(smem_base + BPL(st) + (n * 40 + seg * 8) * 2,
                 g_w1H + ((size_t)(se * D1 + n) * KPAD1 + kc * 32 + seg * 8), 16);
        }
        CP_COMMIT();
    };
    auto issueW2 = [&](int kc, int b) {
        #pragma unroll
        for (int it = 0; it < 6; ++it) {
            int t = tid + it * 256;          // 0..1535
            int p   = t >= 768;
            int rem = t - p * 768;
            int n   = rem >> 2;
            int seg = rem & 3;
            const uint16_t* base = p ? g_w2L : g_w2H;
            cp16(smem_base + WPL(b, p) + (n * 40 + seg * 8) * 2,
                 base + ((size_t)(se * D2 + n) * D1 + kc * 32 + seg * 8), 16);
        }
        CP_COMMIT();
    };
    auto issueW3 = [&](int kc, int b) {
        #pragma unroll
        for (int it = 0; it < 5; ++it) {
            int t = tid + it * 256;          // 0..1279
            int p   = t >= 640;
            int rem = t - p * 640;
            int n   = rem >> 2;
            int seg = rem & 3;
            const uint16_t* base = p ? g_w3L : g_w3H;
            cp16(smem_base + WPL(b, p) + (n * 40 + seg * 8) * 2,
                 base + ((size_t)(se * D3 + n) * D2 + kc * 32 + seg * 8), 16);
        }
        CP_COMMIT();
    };

    // ==================== Layer 1: fp16 2-term, [128 x 1024] @ [1024 x 256] ====================
    {
        const int nB = wn * 64;
        float acc[4][8][4];
        #pragma unroll
        for (int mi = 0; mi < 4; mi++)
            #pragma unroll
            for (int j = 0; j < 8; j++)
                #pragma unroll
                for (int q = 0; q < 4; q++) acc[mi][j][q] = 0.f;

        issueA1(0, 0); issueB1(0, 0);
        for (int kc = 0; kc < NC1; ++kc) {
            const int st = kc & 1;
            if (kc + 1 < NC1) { issueA1(kc + 1, st ^ 1); issueB1(kc + 1, st ^ 1); CP_WAIT1(); }
            else              { CP_WAIT0(); }
            __syncthreads();
            #pragma unroll
            for (int ks = 0; ks < 2; ++ks) {
                const int k0 = ks * 16;
                uint32_t AH[4][4], AL[4][4];
                #pragma unroll
                for (int mi = 0; mi < 4; mi++) {
                    uint32_t aaddr = smem_base + APL(st, 0)
                                   + ((mB + mi * 16 + amrow) * 40 + k0 + akoff) * 2;
                    ldm4(AH[mi], aaddr);
                    ldm4(AL[mi], aaddr + 10240);
                }
                #pragma unroll
                for (int jp = 0; jp < 4; ++jp) {
                    uint32_t baddr = smem_base + BPL(st)
                                   + ((nB + jp * 16 + bnrow) * 40 + k0 + bkoff) * 2;
                    uint32_t BH[4];
                    ldm4(BH, baddr);
                    #pragma unroll
                    for (int mi = 0; mi < 4; mi++) {
                        mma16h(acc[mi][2 * jp],     AH[mi], BH);
                        mma16h(acc[mi][2 * jp],     AL[mi], BH);
                        mma16h(acc[mi][2 * jp + 1], AH[mi], BH + 2);
                        mma16h(acc[mi][2 * jp + 1], AL[mi], BH + 2);
                    }
                }
            }
            __syncthreads();
        }
        issueW2(0, 0);
        // epilogue: bias + CELU -> bf16 h planes (overwrites L1 staging)
        #pragma unroll
        for (int mi = 0; mi < 4; mi++) {
            int r0 = mB + mi * 16 + gid;
            int r1 = r0 + 8;
            #pragma unroll
            for (int j = 0; j < 8; j++) {
                int c = nB + j * 8 + tig * 2;
                float bb0 = __ldg(b1g + c), bb1 = __ldg(b1g + c + 1);
                float v00 = celu01(acc[mi][j][0] + bb0);
                float v01 = celu01(acc[mi][j][1] + bb1);
                float v10 = celu01(acc[mi][j][2] + bb0);
                float v11 = celu01(acc[mi][j][3] + bb1);
                uint32_t h0 = cvt2(v00, v01);
                uint32_t l0 = cvt2(v00 - lo16f(h0), v01 - hi16f(h0));
                uint32_t h1 = cvt2(v10, v11);
                uint32_t l1 = cvt2(v10 - lo16f(h1), v11 - hi16f(h1));
                *(uint32_t*)(smc + HH + (r0 * 264 + c) * 2) = h0;
                *(uint32_t*)(smc + HL + (r0 * 264 + c) * 2) = l0;
                *(uint32_t*)(smc + HH + (r1 * 264 + c) * 2) = h1;
                *(uint32_t*)(smc + HL + (r1 * 264 + c) * 2) = l1;
            }
        }
    }

    // ==================== Layer 2: bf16 3-term, [128 x 256] @ [256 x 192] ====================
    {
        const int nB = wn * 48;
        float acc[4][6][4];
        #pragma unroll
        for (int mi = 0; mi < 4; mi++)
            #pragma unroll
            for (int j = 0; j < 6; j++)
                #pragma unroll
                for (int q = 0; q < 4; q++) acc[mi][j][q] = 0.f;

        for (int kc = 0; kc < NC2; ++kc) {
            if (kc + 1 < NC2) { issueW2(kc + 1, (kc + 1) & 1); CP_WAIT1(); }
            else              { CP_WAIT0(); }
            __syncthreads();
            const int b = kc & 1;
            #pragma unroll
            for (int ks = 0; ks < 2; ++ks) {
                const int kg0 = kc * 32 + ks * 16;
                uint32_t AH[4][4], AL[4][4];
                #pragma unroll
                for (int mi = 0; mi < 4; mi++) {
                    uint32_t aaddr = smem_base + HH
                                   + ((mB + mi * 16 + amrow) * 264 + kg0 + akoff) * 2;
                    ldm4(AH[mi], aaddr);
                    ldm4(AL[mi], aaddr + 67584);
                }
                #pragma unroll
                for (int jp = 0; jp < 3; ++jp) {
                    uint32_t baddr = smem_base + WPL(b, 0)
                                   + ((nB + jp * 16 + bnrow) * 40 + ks * 16 + bkoff) * 2;
                    uint32_t BH[4], BL[4];
                    ldm4(BH, baddr);
                    ldm4(BL, baddr + 15360);
                    #pragma unroll
                    for (int mi = 0; mi < 4; mi++) {
                        mma16(acc[mi][2 * jp],     AH[mi], BH);
                        mma16(acc[mi][2 * jp],     AL[mi], BH);
                        mma16(acc[mi][2 * jp],     AH[mi], BL);
                        mma16(acc[mi][2 * jp + 1], AH[mi], BH + 2);
                        mma16(acc[mi][2 * jp + 1], AL[mi], BH + 2);
                        mma16(acc[mi][2 * jp + 1], AH[mi], BL + 2);
                    }
                }
            }
            __syncthreads();
        }
        issueW3(0, 0);
        #pragma unroll
        for (int mi = 0; mi < 4; mi++) {
            int r0 = mB + mi * 16 + gid;
            int r1 = r0 + 8;
            #pragma unroll
            for (int j = 0; j < 6; j++) {
                int c = nB + j * 8 + tig * 2;
                float bb0 = __ldg(b2g + c), bb1 = __ldg(b2g + c + 1);
                float v00 = celu01(acc[mi][j][0] + bb0);
                float v01 = celu01(acc[mi][j][1] + bb1);
                float v10 = celu01(acc[mi][j][2] + bb0);
                float v11 = celu01(acc[mi][j][3] + bb1);
                uint32_t h0 = cvt2(v00, v01);
                uint32_t l0 = cvt2(v00 - lo16f(h0), v01 - hi16f(h0));
                uint32_t h1 = cvt2(v10, v11);
                uint32_t l1 = cvt2(v10 - lo16f(h1), v11 - hi16f(h1));
                *(uint32_t*)(smc + HH + (r0 * 264 + c) * 2) = h0;
                *(uint32_t*)(smc + HL + (r0 * 264 + c) * 2) = l0;
                *(uint32_t*)(smc + HH + (r1 * 264 + c) * 2) = h1;
                *(uint32_t*)(smc + HL + (r1 * 264 + c) * 2) = l1;
            }
        }
    }

    // ==================== Layer 3: bf16 3-term, [128 x 192] @ [192 x 160] ====================
    float energy = 0.f;
    {
        const int nB = wn * 40;
        float acc[4][5][4];
        #pragma unroll
        for (int mi = 0; mi < 4; mi++)
            #pragma unroll
            for (int j = 0; j < 5; j++)
                #pragma unroll
                for (int q = 0; q < 4; q++) acc[mi][j][q] = 0.f;

        for (int kc = 0; kc < NC3; ++kc) {
            if (kc + 1 < NC3) { issueW3(kc + 1, (kc + 1) & 1); CP_WAIT1(); }
            else              { CP_WAIT0(); }
            __syncthreads();
            const int b = kc & 1;
            #pragma unroll
            for (int ks = 0; ks < 2; ++ks) {
                const int kg0 = kc * 32 + ks * 16;
                uint32_t AH[4][4], AL[4][4];
                #pragma unroll
                for (int mi = 0; mi < 4; mi++) {
                    uint32_t aaddr = smem_base + HH
                                   + ((mB + mi * 16 + amrow) * 264 + kg0 + akoff) * 2;
                    ldm4(AH[mi], aaddr);
                    ldm4(AL[mi], aaddr + 67584);
                }
                #pragma unroll
                for (int jp = 0; jp < 2; ++jp) {
                    uint32_t baddr = smem_base + WPL(b, 0)
                                   + ((nB + jp * 16 + bnrow) * 40 + ks * 16 + bkoff) * 2;
                    uint32_t BH[4], BL[4];
                    ldm4(BH, baddr);
                    ldm4(BL, baddr + 15360);
                    #pragma unroll
                    for (int mi = 0; mi < 4; mi++) {
                        mma16(acc[mi][2 * jp],     AH[mi], BH);
                        mma16(acc[mi][2 * jp],     AL[mi], BH);
                        mma16(acc[mi][2 * jp],     AH[mi], BL);
                        mma16(acc[mi][2 * jp + 1], AH[mi], BH + 2);
                        mma16(acc[mi][2 * jp + 1], AL[mi], BH + 2);
                        mma16(acc[mi][2 * jp + 1], AH[mi], BL + 2);
                    }
                }
                {   // j = 4 (single octet) via ldmatrix.x2
                    uint32_t baddr = smem_base + WPL(b, 0)
                                   + ((nB + 32 + (lane & 7)) * 40 + ks * 16 + bkoff) * 2;
                    uint32_t BH[2], BL[2];
                    ldm2(BH, baddr);
                    ldm2(BL, baddr + 15360);
                    #pragma unroll
                    for (int mi = 0; mi < 4; mi++) {
                        mma16(acc[mi][4], AH[mi], BH);
                        mma16(acc[mi][4], AL[mi], BH);
                        mma16(acc[mi][4], AH[mi], BL);
                    }
                }
            }
            __syncthreads();
        }
        // epilogue: bias + CELU, dot with w4, row-masked
        #pragma unroll
        for (int mi = 0; mi < 4; mi++) {
            int r0 = mB + mi * 16 + gid;
            int r1 = r0 + 8;
            #pragma unroll
            for (int j = 0; j < 5; j++) {
                int n = nB + j * 8 + tig * 2;
                float bb0 = __ldg(b3g + n), bb1 = __ldg(b3g + n + 1);
                float w0  = __ldg(w4g + n), w1  = __ldg(w4g + n + 1);
                if (r0 < valid)
                    energy += celu01(acc[mi][j][0] + bb0) * w0
                            + celu01(acc[mi][j][1] + bb1) * w1;
                if (r1 < valid)
                    energy += celu01(acc[mi][j][2] + bb0) * w0
                            + celu01(acc[mi][j][3] + bb1) * w1;
            }
        }
    }

    red[tid] = energy;
    __syncthreads();
    #pragma unroll
    for (int st = 128; st > 0; st >>= 1) {
        if (tid < st) red[tid] += red[tid + st];
        __syncthreads();
    }
    if (tid == 0) {
        atomicAdd(&g_scratch, (double)(red[0] + (float)valid * B4[se]));
        __threadfence();
        int done = atomicAdd(&g_done, 1);
        if (done == NBLOCKS - 1)
            out[0] = (float)(g_scratch * (1.0 / ENS));
    }
}

extern "C" void kernel_launch(void* const* d_in, const int* in_sizes, int n_in,
                              void* d_out, int out_size)
{
    // Identify inputs by element count (robust to metadata ordering).
    const float *aev = 0, *W1 = 0, *B1 = 0, *W2 = 0, *B2 = 0,
                *W3 = 0, *B3 = 0, *W4 = 0, *B4 = 0;
    const int *idx = 0;
    int n5120 = 0, n50000 = 0;
    for (int i = 0; i < n_in; ++i) {
        switch (in_sizes[i]) {
            case 50400000: aev = (const float*)d_in[i]; break;
            case 8257536:  W1  = (const float*)d_in[i]; break;
            case 8192:     B1  = (const float*)d_in[i]; break;
            case 1572864:  W2  = (const float*)d_in[i]; break;
            case 6144:     B2  = (const float*)d_in[i]; break;
            case 983040:   W3  = (const float*)d_in[i]; break;
            case 5120:
                if (n5120++ == 0) B3 = (const float*)d_in[i];
                else              W4 = (const float*)d_in[i];
                break;
            case 32:       B4  = (const float*)d_in[i]; break;
            case 50000:
                if (n50000++ == 0) { /* species (unused) */ }
                else idx = (const int*)d_in[i];
                break;
            default: break;
        }
    }

    cudaFuncSetAttribute(ani_main,
                         cudaFuncAttributeMaxDynamicSharedMemorySize, SMEM_BYTES);

    prep_all<<<(int)((T_ALL + 255) / 256), 256>>>(aev, W1, W2, W3);

    dim3 grid(ENS, NTILES, NSPECIES);
    ani_main<<<grid, 256, SMEM_BYTES>>>(B1, B2, B3, W4, B4, idx, (float*)d_out);
}

// round 11
// speedup vs baseline: 1.8407x; 1.3742x over previous
#include <cuda_runtime.h>
#include <cuda_fp16.h>
#include <cstdint>

// ---------------- problem constants ----------------
#define NS_PER   12500
#define AEVD     1008
#define KPAD1    1024
#define D1       256
#define D2       192
#define D3       160
#define ENS      8
#define NSPECIES 4
#define TM       128
#define NTILES   98
#define NATOM    50000
#define NSE      32
#define NBLOCKS  (ENS * NTILES * NSPECIES)   // 3136

#define NC1 32    // KPAD1/32
#define NC2 8     // D1/32
#define NC3 6     // D2/32

// ---------------- persistent fp16 plane scratch ----------------
// aev: single fp16 plane; W1/W2/W3: single fp16 plane (transposed [se][n][k]).
__device__ uint16_t g_aevH[(size_t)NATOM * KPAD1];
__device__ uint16_t g_w1H[(size_t)NSE * D1 * KPAD1];
__device__ uint16_t g_w2H[(size_t)NSE * D2 * D1];
__device__ uint16_t g_w3H[(size_t)NSE * D3 * D2];
__device__ double g_scratch;
__device__ int    g_done;

// ---------------- smem layout (bytes) ----------------
#define RI_OFF   0                          // 128 ints
#define RED_OFF  512                        // 256 floats
#define PL       2048
// L1 staging: 2 stages, each [Ah 10240][Bh 20480] = 30720
#define APL(st)  (PL + (st)*30720)
#define BPL(st)  (PL + (st)*30720 + 10240)
// h planes (fp16 hi/lo) overwrite staging after L1: [128][264] per plane
#define HH       PL
#define HL       (PL + 67584)
// W2/W3 single-plane 2-stage staging after H region (stride 40, K=32 chunks)
#define WPL(b)   (PL + 135168 + (b)*15360)
#define SMEM_BYTES (PL + 135168 + 30720)    // 167936

// ---------------- helpers ----------------
__device__ __forceinline__ uint32_t cvt2h(float v0, float v1) { // f16x2: v0->lo, v1->hi
    uint32_t r;
    asm("cvt.rn.f16x2.f32 %0, %1, %2;" : "=r"(r) : "f"(v1), "f"(v0));
    return r;
}
__device__ __forceinline__ float h2lo(uint32_t h) {
    __half2 hh = *reinterpret_cast<__half2*>(&h);
    return __half2float(hh.x);
}
__device__ __forceinline__ float h2hi(uint32_t h) {
    __half2 hh = *reinterpret_cast<__half2*>(&h);
    return __half2float(hh.y);
}

__device__ __forceinline__ float celu01(float x) {
    return x > 0.f ? x : 0.1f * (__expf(x * 10.f) - 1.f);
}

__device__ __forceinline__ void mma16h(float d[4], const uint32_t a[4], const uint32_t b[2]) {
    asm volatile(
        "mma.sync.aligned.m16n8k16.row.col.f32.f16.f16.f32 "
        "{%0,%1,%2,%3},{%4,%5,%6,%7},{%8,%9},{%0,%1,%2,%3};\n"
        : "+f"(d[0]), "+f"(d[1]), "+f"(d[2]), "+f"(d[3])
        : "r"(a[0]), "r"(a[1]), "r"(a[2]), "r"(a[3]), "r"(b[0]), "r"(b[1]));
}

__device__ __forceinline__ void ldm4(uint32_t* r, uint32_t addr) {
    asm volatile("ldmatrix.sync.aligned.m8n8.x4.shared.b16 {%0,%1,%2,%3}, [%4];"
                 : "=r"(r[0]), "=r"(r[1]), "=r"(r[2]), "=r"(r[3]) : "r"(addr));
}
__device__ __forceinline__ void ldm2(uint32_t* r, uint32_t addr) {
    asm volatile("ldmatrix.sync.aligned.m8n8.x2.shared.b16 {%0,%1}, [%2];"
                 : "=r"(r[0]), "=r"(r[1]) : "r"(addr));
}

__device__ __forceinline__ void cp16(uint32_t dst, const void* src, int szbytes) {
    asm volatile("cp.async.ca.shared.global [%0], [%1], 16, %2;\n"
                 :: "r"(dst), "l"(src), "r"(szbytes));
}
#define CP_COMMIT()  asm volatile("cp.async.commit_group;\n" ::)
#define CP_WAIT1()   asm volatile("cp.async.wait_group 1;\n" ::)
#define CP_WAIT0()   asm volatile("cp.async.wait_group 0;\n" ::)

// ---------------- merged pre-pass ----------------
#define T_AEV ((long)NATOM * (KPAD1 / 2))
#define T_W1  ((long)NSE * D1 * (KPAD1 / 2))
#define T_W2  ((long)NSE * D2 * (D1 / 2))
#define T_W3  ((long)NSE * D3 * (D2 / 2))
#define T_ALL (T_AEV + T_W1 + T_W2 + T_W3)

__global__ void prep_all(const float* __restrict__ aev, const float* __restrict__ W1,
                         const float* __restrict__ W2, const float* __restrict__ W3)
{
    long t = (long)blockIdx.x * 256 + threadIdx.x;
    if (t == 0) { g_scratch = 0.0; g_done = 0; }
    if (t >= T_ALL) return;

    if (t < T_AEV) {
        // aev -> single fp16 plane
        long a  = t / (KPAD1 / 2);
        int  kp = (int)(t - a * (KPAD1 / 2));
        int  k  = 2 * kp;
        float v0 = (k     < AEVD) ? aev[(size_t)a * AEVD + k]     : 0.f;
        float v1 = (k + 1 < AEVD) ? aev[(size_t)a * AEVD + k + 1] : 0.f;
        ((uint32_t*)g_aevH)[t] = cvt2h(v0, v1);
        return;
    }
    // Weights -> single fp16 plane, transposed [se][n][kpad]
    const float* W; uint16_t* dH; int K, N, Kpad; long u;
    if (t < T_AEV + T_W1)             { u = t - T_AEV;               W = W1; dH = g_w1H; K = AEVD; N = D1; Kpad = KPAD1; }
    else if (t < T_AEV + T_W1 + T_W2) { u = t - T_AEV - T_W1;        W = W2; dH = g_w2H; K = D1;   N = D2; Kpad = D1; }
    else                              { u = t - T_AEV - T_W1 - T_W2; W = W3; dH = g_w3H; K = D2;   N = D3; Kpad = D2; }
    int n  = (int)(u % N);
    long r = u / N;
    int kp = (int)(r % (Kpad / 2));
    int se = (int)(r / (Kpad / 2));
    int k  = 2 * kp;
    float v0 = (k     < K) ? W[((size_t)se * K + k) * N + n]     : 0.f;
    float v1 = (k + 1 < K) ? W[((size_t)se * K + k + 1) * N + n] : 0.f;
    ((uint32_t*)dH)[((size_t)se * N + n) * (Kpad / 2) + kp] = cvt2h(v0, v1);
}

// ---------------- main fused kernel (256 threads, 2x4 warps; R6 structure) ----------------
__global__ void __launch_bounds__(256, 1)
ani_main(const float* __restrict__ B1, const float* __restrict__ B2,
         const float* __restrict__ B3, const float* __restrict__ W4,
         const float* __restrict__ B4, const int* __restrict__ idx,
         float* __restrict__ out)
{
    extern __shared__ char smc[];
    const uint32_t smem_base = (uint32_t)__cvta_generic_to_shared(smc);
    int*   rowIdx = (int*)(smc + RI_OFF);
    float* red    = (float*)(smc + RED_OFF);

    const int e    = blockIdx.x;
    const int tile = blockIdx.y;
    const int s    = blockIdx.z;
    const int se   = s * ENS + e;

    const int tid  = threadIdx.x;
    const int lane = tid & 31;
    const int warp = tid >> 5;
    const int gid  = lane >> 2;
    const int tig  = lane & 3;
    const int wm   = warp & 1;
    const int wn   = warp >> 1;     // 0..3
    const int mB   = wm * 64;

    const int amrow = (lane & 7) + (lane & 8);
    const int akoff = (lane & 16) >> 1;
    const int bnrow = (lane & 7) + ((lane & 16) >> 1);
    const int bkoff = lane & 8;

    const int tileBase = tile * TM;
    const int valid    = min(TM, NS_PER - tileBase);

    if (tid < TM)
        rowIdx[tid] = (tid < valid) ? idx[s * NS_PER + tileBase + tid] : -1;
    __syncthreads();

    const float* b1g = B1 + (size_t)se * D1;
    const float* b2g = B2 + (size_t)se * D2;
    const float* b3g = B3 + (size_t)se * D3;
    const float* w4g = W4 + (size_t)se * D3;

    // ---------------- cp.async issue helpers ----------------
    auto issueA1 = [&](int kc, int st) {
        #pragma unroll
        for (int it = 0; it < 2; ++it) {
            int t = tid + it * 256;          // 0..511 : 128 rows x 4 segs
            int r   = t >> 2;
            int seg = t & 3;
            int g   = rowIdx[r];
            const uint16_t* src = g_aevH + ((size_t)(g < 0 ? 0 : g) * KPAD1 + kc * 32 + seg * 8);
            cp16(smem_base + APL(st) + (r * 40 + seg * 8) * 2, src, g >= 0 ? 16 : 0);
        }
    };
    auto issueB1 = [&](int kc, int st) {
        #pragma unroll
        for (int it = 0; it < 4; ++it) {
            int t = tid + it * 256;          // 0..1023 : 256 n x 4 segs
            int n   = t >> 2;
            int seg = t & 3;
            cp16(smem_base + BPL(st) + (n * 40 + seg * 8) * 2,
                 g_w1H + ((size_t)(se * D1 + n) * KPAD1 + kc * 32 + seg * 8), 16);
        }
        CP_COMMIT();
    };
    auto issueW2 = [&](int kc, int b) {
        #pragma unroll
        for (int it = 0; it < 3; ++it) {
            int t = tid + it * 256;          // 0..767 : 192 n x 4 segs
            int n   = t >> 2;
            int seg = t & 3;
            cp16(smem_base + WPL(b) + (n * 40 + seg * 8) * 2,
                 g_w2H + ((size_t)(se * D2 + n) * D1 + kc * 32 + seg * 8), 16);
        }
        CP_COMMIT();
    };
    auto issueW3 = [&](int kc, int b) {
        #pragma unroll
        for (int it = 0; it < 3; ++it) {
            int t = tid + it * 256;          // 0..639 : 160 n x 4 segs
            if (t < 640) {
                int n   = t >> 2;
                int seg = t & 3;
                cp16(smem_base + WPL(b) + (n * 40 + seg * 8) * 2,
                     g_w3H + ((size_t)(se * D3 + n) * D2 + kc * 32 + seg * 8), 16);
            }
        }
        CP_COMMIT();
    };

    // ==================== Layer 1: fp16 1-term, [128 x 1024] @ [1024 x 256] ====================
    {
        const int nB = wn * 64;
        float acc[4][8][4];
        #pragma unroll
        for (int mi = 0; mi < 4; mi++)
            #pragma unroll
            for (int j = 0; j < 8; j++)
                #pragma unroll
                for (int q = 0; q < 4; q++) acc[mi][j][q] = 0.f;

        issueA1(0, 0); issueB1(0, 0);
        for (int kc = 0; kc < NC1; ++kc) {
            const int st = kc & 1;
            if (kc + 1 < NC1) { issueA1(kc + 1, st ^ 1); issueB1(kc + 1, st ^ 1); CP_WAIT1(); }
            else              { CP_WAIT0(); }
            __syncthreads();
            #pragma unroll
            for (int ks = 0; ks < 2; ++ks) {
                const int k0 = ks * 16;
                uint32_t AH[4][4];
                #pragma unroll
                for (int mi = 0; mi < 4; mi++) {
                    uint32_t aaddr = smem_base + APL(st)
                                   + ((mB + mi * 16 + amrow) * 40 + k0 + akoff) * 2;
                    ldm4(AH[mi], aaddr);
                }
                #pragma unroll
                for (int jp = 0; jp < 4; ++jp) {
                    uint32_t baddr = smem_base + BPL(st)
                                   + ((nB + jp * 16 + bnrow) * 40 + k0 + bkoff) * 2;
                    uint32_t BH[4];
                    ldm4(BH, baddr);
                    #pragma unroll
                    for (int mi = 0; mi < 4; mi++) {
                        mma16h(acc[mi][2 * jp],     AH[mi], BH);
                        mma16h(acc[mi][2 * jp + 1], AH[mi], BH + 2);
                    }
                }
            }
            __syncthreads();
        }
        issueW2(0, 0);
        // epilogue: bias + CELU -> fp16 h hi/lo planes (overwrites L1 staging)
        #pragma unroll
        for (int mi = 0; mi < 4; mi++) {
            int r0 = mB + mi * 16 + gid;
            int r1 = r0 + 8;
            #pragma unroll
            for (int j = 0; j < 8; j++) {
                int c = nB + j * 8 + tig * 2;
                float bb0 = __ldg(b1g + c), bb1 = __ldg(b1g + c + 1);
                float v00 = celu01(acc[mi][j][0] + bb0);
                float v01 = celu01(acc[mi][j][1] + bb1);
                float v10 = celu01(acc[mi][j][2] + bb0);
                float v11 = celu01(acc[mi][j][3] + bb1);
                uint32_t h0 = cvt2h(v00, v01);
                uint32_t l0 = cvt2h(v00 - h2lo(h0), v01 - h2hi(h0));
                uint32_t h1 = cvt2h(v10, v11);
                uint32_t l1 = cvt2h(v10 - h2lo(h1), v11 - h2hi(h1));
                *(uint32_t*)(smc + HH + (r0 * 264 + c) * 2) = h0;
                *(uint32_t*)(smc + HL + (r0 * 264 + c) * 2) = l0;
                *(uint32_t*)(smc + HH + (r1 * 264 + c) * 2) = h1;
                *(uint32_t*)(smc + HL + (r1 * 264 + c) * 2) = l1;
            }
        }
    }

    // ==================== Layer 2: h 2-term x W 1-term fp16, [128x256]@[256x192] ====================
    {
        const int nB = wn * 48;
        float acc[4][6][4];
        #pragma unroll
        for (int mi = 0; mi < 4; mi++)
            #pragma unroll
            for (int j = 0; j < 6; j++)
                #pragma unroll
                for (int q = 0; q < 4; q++) acc[mi][j][q] = 0.f;

        for (int kc = 0; kc < NC2; ++kc) {
            if (kc + 1 < NC2) { issueW2(kc + 1, (kc + 1) & 1); CP_WAIT1(); }
            else              { CP_WAIT0(); }
            __syncthreads();
            const int b = kc & 1;
            #pragma unroll
            for (int ks = 0; ks < 2; ++ks) {
                const int kg0 = kc * 32 + ks * 16;
                uint32_t AH[4][4], AL[4][4];
                #pragma unroll
                for (int mi = 0; mi < 4; mi++) {
                    uint32_t aaddr = smem_base + HH
                                   + ((mB + mi * 16 + amrow) * 264 + kg0 + akoff) * 2;
                    ldm4(AH[mi], aaddr);
                    ldm4(AL[mi], aaddr + 67584);
                }
                #pragma unroll
                for (int jp = 0; jp < 3; ++jp) {
                    uint32_t baddr = smem_base + WPL(b)
                                   + ((nB + jp * 16 + bnrow) * 40 + ks * 16 + bkoff) * 2;
                    uint32_t BH[4];
                    ldm4(BH, baddr);
                    #pragma unroll
                    for (int mi = 0; mi < 4; mi++) {
                        mma16h(acc[mi][2 * jp],     AH[mi], BH);
                        mma16h(acc[mi][2 * jp],     AL[mi], BH);
                        mma16h(acc[mi][2 * jp + 1], AH[mi], BH + 2);
                        mma16h(acc[mi][2 * jp + 1], AL[mi], BH + 2);
                    }
                }
            }
            __syncthreads();
        }
        issueW3(0, 0);
        // epilogue -> h2 planes (cols 0..191)
        #pragma unroll
        for (int mi = 0; mi < 4; mi++) {
            int r0 = mB + mi * 16 + gid;
            int r1 = r0 + 8;
            #pragma unroll
            for (int j = 0; j < 6; j++) {
                int c = nB + j * 8 + tig * 2;
                float bb0 = __ldg(b2g + c), bb1 = __ldg(b2g + c + 1);
                float v00 = celu01(acc[mi][j][0] + bb0);
                float v01 = celu01(acc[mi][j][1] + bb1);
                float v10 = celu01(acc[mi][j][2] + bb0);
                float v11 = celu01(acc[mi][j][3] + bb1);
                uint32_t h0 = cvt2h(v00, v01);
                uint32_t l0 = cvt2h(v00 - h2lo(h0), v01 - h2hi(h0));
                uint32_t h1 = cvt2h(v10, v11);
                uint32_t l1 = cvt2h(v10 - h2lo(h1), v11 - h2hi(h1));
                *(uint32_t*)(smc + HH + (r0 * 264 + c) * 2) = h0;
                *(uint32_t*)(smc + HL + (r0 * 264 + c) * 2) = l0;
                *(uint32_t*)(smc + HH + (r1 * 264 + c) * 2) = h1;
                *(uint32_t*)(smc + HL + (r1 * 264 + c) * 2) = l1;
            }
        }
    }

    // ==================== Layer 3: h 2-term x W 1-term fp16, [128x192]@[192x160] ====================
    float energy = 0.f;
    {
        const int nB = wn * 40;
        float acc[4][5][4];
        #pragma unroll
        for (int mi = 0; mi < 4; mi++)
            #pragma unroll
            for (int j = 0; j < 5; j++)
                #pragma unroll
                for (int q = 0; q < 4; q++) acc[mi][j][q] = 0.f;

        for (int kc = 0; kc < NC3; ++kc) {
            if (kc + 1 < NC3) { issueW3(kc + 1, (kc + 1) & 1); CP_WAIT1(); }
            else              { CP_WAIT0(); }
            __syncthreads();
            const int b = kc & 1;
            #pragma unroll
            for (int ks = 0; ks < 2; ++ks) {
                const int kg0 = kc * 32 + ks * 16;
                uint32_t AH[4][4], AL[4][4];
                #pragma unroll
                for (int mi = 0; mi < 4; mi++) {
                    uint32_t aaddr = smem_base + HH
                                   + ((mB + mi * 16 + amrow) * 264 + kg0 + akoff) * 2;
                    ldm4(AH[mi], aaddr);
                    ldm4(AL[mi], aaddr + 67584);
                }
                #pragma unroll
                for (int jp = 0; jp < 2; ++jp) {
                    uint32_t baddr = smem_base + WPL(b)
                                   + ((nB + jp * 16 + bnrow) * 40 + ks * 16 + bkoff) * 2;
                    uint32_t BH[4];
                    ldm4(BH, baddr);
                    #pragma unroll
                    for (int mi = 0; mi < 4; mi++) {
                        mma16h(acc[mi][2 * jp],     AH[mi], BH);
                        mma16h(acc[mi][2 * jp],     AL[mi], BH);
                        mma16h(acc[mi][2 * jp + 1], AH[mi], BH + 2);
                        mma16h(acc[mi][2 * jp + 1], AL[mi], BH + 2);
                    }
                }
                {   // j = 4 (single octet) via ldmatrix.x2
                    uint32_t baddr = smem_base + WPL(b)
                                   + ((nB + 32 + (lane & 7)) * 40 + ks * 16 + bkoff) * 2;
                    uint32_t BH[2];
                    ldm2(BH, baddr);
                    #pragma unroll
                    for (int mi = 0; mi < 4; mi++) {
                        mma16h(acc[mi][4], AH[mi], BH);
                        mma16h(acc[mi][4], AL[mi], BH);
                    }
                }
            }
            __syncthreads();
        }
        // epilogue: bias + CELU, dot with w4, row-masked
        #pragma unroll
        for (int mi = 0; mi < 4; mi++) {
            int r0 = mB + mi * 16 + gid;
            int r1 = r0 + 8;
            #pragma unroll
            for (int j = 0; j < 5; j++) {
                int n = nB + j * 8 + tig * 2;
                float bb0 = __ldg(b3g + n), bb1 = __ldg(b3g + n + 1);
                float w0  = __ldg(w4g + n), w1  = __ldg(w4g + n + 1);
                if (r0 < valid)
                    energy += celu01(acc[mi][j][0] + bb0) * w0
                            + celu01(acc[mi][j][1] + bb1) * w1;
                if (r1 < valid)
                    energy += celu01(acc[mi][j][2] + bb0) * w0
                            + celu01(acc[mi][j][3] + bb1) * w1;
            }
        }
    }

    red[tid] = energy;
    __syncthreads();
    #pragma unroll
    for (int st = 128; st > 0; st >>= 1) {
        if (tid < st) red[tid] += red[tid + st];
        __syncthreads();
    }
    if (tid == 0) {
        atomicAdd(&g_scratch, (double)(red[0] + (float)valid * B4[se]));
        __threadfence();
        int done = atomicAdd(&g_done, 1);
        if (done == NBLOCKS - 1)
            out[0] = (float)(g_scratch * (1.0 / ENS));
    }
}

extern "C" void kernel_launch(void* const* d_in, const int* in_sizes, int n_in,
                              void* d_out, int out_size)
{
    // Identify inputs by element count (robust to metadata ordering).
    const float *aev = 0, *W1 = 0, *B1 = 0, *W2 = 0, *B2 = 0,
                *W3 = 0, *B3 = 0, *W4 = 0, *B4 = 0;
    const int *idx = 0;
    int n5120 = 0, n50000 = 0;
    for (int i = 0; i < n_in; ++i) {
        switch (in_sizes[i]) {
            case 50400000: aev = (const float*)d_in[i]; break;
            case 8257536:  W1  = (const float*)d_in[i]; break;
            case 8192:     B1  = (const float*)d_in[i]; break;
            case 1572864:  W2  = (const float*)d_in[i]; break;
            case 6144:     B2  = (const float*)d_in[i]; break;
            case 983040:   W3  = (const float*)d_in[i]; break;
            case 5120:
                if (n5120++ == 0) B3 = (const float*)d_in[i];
                else              W4 = (const float*)d_in[i];
                break;
            case 32:       B4  = (const float*)d_in[i]; break;
            case 50000:
                if (n50000++ == 0) { /* species (unused) */ }
                else idx = (const int*)d_in[i];
                break;
            default: break;
        }
    }

    cudaFuncSetAttribute(ani_main,
                         cudaFuncAttributeMaxDynamicSharedMemorySize, SMEM_BYTES);

    prep_all<<<(int)((T_ALL + 255) / 256), 256>>>(aev, W1, W2, W3);

    dim3 grid(ENS, NTILES, NSPECIES);
    ani_main<<<grid, 256, SMEM_BYTES>>>(B1, B2, B3, W4, B4, idx, (float*)d_out);
}